// round 1
// baseline (speedup 1.0000x reference)
#include <cuda_runtime.h>
#include <math.h>

// Problem dims (fixed by reference)
#define BB 8
#define SS 2048
#define DM 1024
#define DK 512
#define DV 512

// Scratch (static device allocations are allowed; cudaMalloc is not)
__device__ float g_Q[BB * SS * DK];            // 33.5 MB
__device__ float g_K[BB * SS * DK];            // 33.5 MB
__device__ float g_V[BB * SS * DV];            // 33.5 MB
__device__ float g_S[(size_t)BB * SS * SS];    // 134 MB, reused in-place for probs

// ---------------------------------------------------------------------------
// Generic tiled SGEMM: C = A * B (or A * B^T when TB)
//   A: [M x K] row-major
//   B: !TB -> [K x N] row-major ; TB -> [N x K] row-major (C = A B^T)
//   CSKIP: skip blocks strictly above the causal diagonal (scores GEMM)
//   CKLIM: truncate K-loop at bm0+BM (attn rows are zero beyond the diagonal)
// Requires: M % BM == 0, N % BN == 0, K % BK == 0 (true for all our shapes)
// ---------------------------------------------------------------------------
template <int BM, int BN, int BK, int TM, int TN, bool TB, bool CSKIP, bool CKLIM>
__global__ __launch_bounds__(256) void gemm_k(
    const float* __restrict__ A, const float* __restrict__ B, float* __restrict__ C,
    int M, int N, int K, size_t sA, size_t sB, size_t sC)
{
    const int bn0 = blockIdx.x * BN;
    const int bm0 = blockIdx.y * BM;
    if (CSKIP && bn0 >= bm0 + BM) return;  // tile fully above causal diagonal: never read

    A += (size_t)blockIdx.z * sA;
    B += (size_t)blockIdx.z * sB;
    C += (size_t)blockIdx.z * sC;

    __shared__ float As[BK][BM];
    __shared__ float Bs[BK][BN];

    const int tid  = threadIdx.x;
    const int tcol = tid % (BN / TN);
    const int trow = tid / (BN / TN);

    float acc[TM][TN] = {};
    float ar[TM], br[TN];

    int kEnd = K;
    if (CKLIM) { int lim = bm0 + BM; kEnd = (lim < K) ? lim : K; }

    for (int k0 = 0; k0 < kEnd; k0 += BK) {
        // --- load A tile [BM x BK], store transposed As[kk][m] ---
        #pragma unroll
        for (int l = 0; l < (BM * BK) / (256 * 4); ++l) {
            int flat = (tid + l * 256) * 4;
            int m = flat / BK, kk = flat % BK;
            float4 v = *reinterpret_cast<const float4*>(A + (size_t)(bm0 + m) * K + k0 + kk);
            As[kk + 0][m] = v.x; As[kk + 1][m] = v.y;
            As[kk + 2][m] = v.z; As[kk + 3][m] = v.w;
        }
        // --- load B tile ---
        if (!TB) {
            #pragma unroll
            for (int l = 0; l < (BK * BN) / (256 * 4); ++l) {
                int flat = (tid + l * 256) * 4;
                int kk = flat / BN, n = flat % BN;
                float4 v = *reinterpret_cast<const float4*>(B + (size_t)(k0 + kk) * N + bn0 + n);
                *reinterpret_cast<float4*>(&Bs[kk][n]) = v;
            }
        } else {
            #pragma unroll
            for (int l = 0; l < (BK * BN) / (256 * 4); ++l) {
                int flat = (tid + l * 256) * 4;
                int n = flat / BK, kk = flat % BK;
                float4 v = *reinterpret_cast<const float4*>(B + (size_t)(bn0 + n) * K + k0 + kk);
                Bs[kk + 0][n] = v.x; Bs[kk + 1][n] = v.y;
                Bs[kk + 2][n] = v.z; Bs[kk + 3][n] = v.w;
            }
        }
        __syncthreads();

        #pragma unroll
        for (int kk = 0; kk < BK; ++kk) {
            #pragma unroll
            for (int i = 0; i < TM; ++i) ar[i] = As[kk][trow * TM + i];
            #pragma unroll
            for (int j = 0; j < TN; ++j) br[j] = Bs[kk][tcol * TN + j];
            #pragma unroll
            for (int i = 0; i < TM; ++i)
                #pragma unroll
                for (int j = 0; j < TN; ++j)
                    acc[i][j] = fmaf(ar[i], br[j], acc[i][j]);
        }
        __syncthreads();
    }

    #pragma unroll
    for (int i = 0; i < TM; ++i) {
        size_t off = (size_t)(bm0 + trow * TM + i) * N + bn0 + tcol * TN;
        #pragma unroll
        for (int j = 0; j < TN; j += 4) {
            float4 v = make_float4(acc[i][j], acc[i][j + 1], acc[i][j + 2], acc[i][j + 3]);
            *reinterpret_cast<float4*>(C + off + j) = v;
        }
    }
}

// ---------------------------------------------------------------------------
// Fused mask + softmax, in place on g_S. One CTA (256 threads) per row.
// Row slice held in registers -> one global read + one write per element.
// masks: int32, nonzero == padded
// ---------------------------------------------------------------------------
__global__ __launch_bounds__(256) void softmax_k(
    float* __restrict__ S,
    const int* __restrict__ qpad, const int* __restrict__ kpad, float scale)
{
    const int r = blockIdx.x;          // 0 .. BB*SS-1
    const int b = r >> 11;             // SS = 2048
    const int i = r & (SS - 1);
    float* row = S + (size_t)r * SS;
    const int* kp = kpad + b * SS;
    const bool qp = (qpad[r] != 0);
    const int tid = threadIdx.x;

    float x[8];
    float m = -INFINITY;
    #pragma unroll
    for (int u = 0; u < 8; ++u) {
        int j = tid + u * 256;
        bool valid = (!qp) && (j <= i) && (kp[j] == 0);
        x[u] = valid ? row[j] * scale : -INFINITY;
        m = fmaxf(m, x[u]);
    }

    __shared__ float redm[8];
    __shared__ float reds[8];
    const int lane = tid & 31, warp = tid >> 5;

    #pragma unroll
    for (int o = 16; o; o >>= 1) m = fmaxf(m, __shfl_xor_sync(0xffffffffu, m, o));
    if (lane == 0) redm[warp] = m;
    __syncthreads();
    float bm = -INFINITY;
    #pragma unroll
    for (int w = 0; w < 8; ++w) bm = fmaxf(bm, redm[w]);

    if (bm == -INFINITY) {  // fully masked row -> zeros (matches NaN->0 in reference)
        #pragma unroll
        for (int u = 0; u < 8; ++u) row[tid + u * 256] = 0.0f;
        return;
    }

    float e[8];
    float s = 0.0f;
    #pragma unroll
    for (int u = 0; u < 8; ++u) {
        e[u] = (x[u] == -INFINITY) ? 0.0f : __expf(x[u] - bm);
        s += e[u];
    }
    #pragma unroll
    for (int o = 16; o; o >>= 1) s += __shfl_xor_sync(0xffffffffu, s, o);
    if (lane == 0) reds[warp] = s;
    __syncthreads();
    float bs = 0.0f;
    #pragma unroll
    for (int w = 0; w < 8; ++w) bs += reds[w];

    const float rinv = 1.0f / bs;
    #pragma unroll
    for (int u = 0; u < 8; ++u) row[tid + u * 256] = e[u] * rinv;
}

// ---------------------------------------------------------------------------
extern "C" void kernel_launch(void* const* d_in, const int* in_sizes, int n_in,
                              void* d_out, int out_size)
{
    const float* sq   = (const float*)d_in[0];   // [B,S,DM]
    const float* skv  = (const float*)d_in[1];   // [B,S,DM]
    const int*   qpad = (const int*)d_in[2];     // [B,S] bool->int32
    const int*   kpad = (const int*)d_in[3];     // [B,S]
    const float* Wq   = (const float*)d_in[4];   // [DM,DK]
    const float* Wk   = (const float*)d_in[5];
    const float* Wv   = (const float*)d_in[6];
    float* out = (float*)d_out;                  // [B,S,DV]

    float *Qb, *Kb, *Vb, *Sb;
    cudaGetSymbolAddress((void**)&Qb, g_Q);
    cudaGetSymbolAddress((void**)&Kb, g_K);
    cudaGetSymbolAddress((void**)&Vb, g_V);
    cudaGetSymbolAddress((void**)&Sb, g_S);

    const dim3 blk(256);
    const int Mproj = BB * SS;  // 16384

    // Projections: Q = sq*Wq, K = skv*Wk, V = skv*Wv
    gemm_k<128, 128, 16, 8, 8, false, false, false>
        <<<dim3(DK / 128, Mproj / 128, 1), blk>>>(sq,  Wq, Qb, Mproj, DK, DM, 0, 0, 0);
    gemm_k<128, 128, 16, 8, 8, false, false, false>
        <<<dim3(DK / 128, Mproj / 128, 1), blk>>>(skv, Wk, Kb, Mproj, DK, DM, 0, 0, 0);
    gemm_k<128, 128, 16, 8, 8, false, false, false>
        <<<dim3(DV / 128, Mproj / 128, 1), blk>>>(skv, Wv, Vb, Mproj, DV, DM, 0, 0, 0);

    // Scores: S_b = Q_b * K_b^T (batched, causal tile-skip)
    gemm_k<128, 128, 16, 8, 8, true, true, false>
        <<<dim3(SS / 128, SS / 128, BB), blk>>>(Qb, Kb, Sb, SS, SS, DK,
            (size_t)SS * DK, (size_t)SS * DK, (size_t)SS * SS);

    // Fused mask + softmax, in place
    const float scale = 0.044194173824159216f;  // 1/sqrt(512)
    softmax_k<<<BB * SS, 256>>>(Sb, qpad, kpad, scale);

    // Out: O_b = P_b * V_b (batched, K-loop truncated at causal diagonal)
    gemm_k<128, 128, 16, 8, 8, false, false, true>
        <<<dim3(DV / 128, SS / 128, BB), blk>>>(Sb, Vb, out, SS, DV, SS,
            (size_t)SS * SS, (size_t)SS * DV, (size_t)SS * DV);
}

// round 4
// speedup vs baseline: 2.5075x; 2.5075x over previous
#include <cuda_runtime.h>
#include <cuda_bf16.h>
#include <stdint.h>
#include <math.h>

#define BB 8
#define SS 2048
#define DM 1024
#define DK 512
#define DV 512
#define MTOK (BB*SS)   // 16384

// ---------------- scratch (static device allocations) ----------------
__device__ __align__(256) float         g_S  [(size_t)BB*SS*SS];      // 134 MB scores
__device__ __align__(256) __nv_bfloat16 g_sqh[(size_t)MTOK*DM];
__device__ __align__(256) __nv_bfloat16 g_sql[(size_t)MTOK*DM];
__device__ __align__(256) __nv_bfloat16 g_kvh[(size_t)MTOK*DM];
__device__ __align__(256) __nv_bfloat16 g_kvl[(size_t)MTOK*DM];
__device__ __align__(256) __nv_bfloat16 g_wqh[(size_t)DK*DM];
__device__ __align__(256) __nv_bfloat16 g_wql[(size_t)DK*DM];
__device__ __align__(256) __nv_bfloat16 g_wkh[(size_t)DK*DM];
__device__ __align__(256) __nv_bfloat16 g_wkl[(size_t)DK*DM];
__device__ __align__(256) __nv_bfloat16 g_wvh[(size_t)DV*DM];
__device__ __align__(256) __nv_bfloat16 g_wvl[(size_t)DV*DM];
__device__ __align__(256) __nv_bfloat16 g_qh [(size_t)MTOK*DK];
__device__ __align__(256) __nv_bfloat16 g_ql [(size_t)MTOK*DK];
__device__ __align__(256) __nv_bfloat16 g_kh [(size_t)MTOK*DK];
__device__ __align__(256) __nv_bfloat16 g_kl [(size_t)MTOK*DK];
__device__ __align__(256) __nv_bfloat16 g_vth[(size_t)DV*MTOK];      // V^T: [512 x 16384]
__device__ __align__(256) __nv_bfloat16 g_vtl[(size_t)DV*MTOK];
__device__ __align__(256) __nv_bfloat16 g_ph [(size_t)MTOK*SS];      // P hi
__device__ __align__(256) __nv_bfloat16 g_pl [(size_t)MTOK*SS];      // P lo

// ---------------- portable PTX helpers (sm_80+ instructions only) ----------
__device__ __forceinline__ uint32_t s2u(const void* p) {
    return (uint32_t)__cvta_generic_to_shared(p);
}

#define CPA16(dst, src) \
    asm volatile("cp.async.cg.shared.global [%0], [%1], 16;" :: "r"(dst), "l"(src))

#define LDSM_X4(r, addr) \
    asm volatile("ldmatrix.sync.aligned.m8n8.x4.shared.b16 {%0,%1,%2,%3}, [%4];" \
        : "=r"((r)[0]), "=r"((r)[1]), "=r"((r)[2]), "=r"((r)[3]) : "r"(addr))

#define LDSM_X2(r, addr) \
    asm volatile("ldmatrix.sync.aligned.m8n8.x2.shared.b16 {%0,%1}, [%2];" \
        : "=r"((r)[0]), "=r"((r)[1]) : "r"(addr))

#define MMA16816(d, a, b) \
    asm volatile("mma.sync.aligned.m16n8k16.row.col.f32.bf16.bf16.f32 " \
        "{%0,%1,%2,%3}, {%4,%5,%6,%7}, {%8,%9}, {%0,%1,%2,%3};" \
        : "+f"((d)[0]), "+f"((d)[1]), "+f"((d)[2]), "+f"((d)[3]) \
        : "r"((a)[0]), "r"((a)[1]), "r"((a)[2]), "r"((a)[3]), \
          "r"((b)[0]), "r"((b)[1]))

// ---------------------------------------------------------------------------
// bf16 MMA GEMM:  C[M x N] = sum over 3 segments of Aseg[M x segK] * Bseg[N x segK]^T
//   seg 0: (A0,B0)  seg 1: (A1,B0)  seg 2: (A0,B1)     (3-term bf16 split)
//   Operands K-major row-major bf16. 128x128 CTA tile, BK=32, double-buffered.
//   CSKIP: skip tiles strictly above causal diagonal
//   KTRUNC: per-segment K truncated at bm0+128 (attn*V causal)
//   EPI: 0 -> fp32 to Cf ; 1 -> bf16 hi/lo split to Ch/Cl
// Smem chunk layout: row-major 128 x 32 bf16, 16B chunk c stored at c^((row>>1)&3)
// ---------------------------------------------------------------------------
template <bool CSKIP, bool KTRUNC, int EPI>
__global__ void __launch_bounds__(256, 2) mma_gemm(
    const __nv_bfloat16* __restrict__ A0, const __nv_bfloat16* __restrict__ A1,
    const __nv_bfloat16* __restrict__ B0, const __nv_bfloat16* __restrict__ B1,
    float* __restrict__ Cf, __nv_bfloat16* __restrict__ Ch, __nv_bfloat16* __restrict__ Cl,
    int segK, int ldA, int ldB, int ldC,
    long long sA, long long sB, long long sC)
{
    __shared__ __align__(128) __nv_bfloat16 smA[2][128 * 32];
    __shared__ __align__(128) __nv_bfloat16 smB[2][128 * 32];

    const int bn0 = blockIdx.x * 128;
    const int bm0 = blockIdx.y * 128;
    if (CSKIP && bn0 >= bm0 + 128) return;

    const long long z = blockIdx.z;
    A0 += z * sA; A1 += z * sA; B0 += z * sB; B1 += z * sB;

    const int tid = threadIdx.x, wid = tid >> 5, lane = tid & 31;
    const int warp_m = (wid >> 2) * 64;   // 0 or 64
    const int warp_n = (wid & 3) * 32;    // 0,32,64,96

    int kEnd = segK;
    if (KTRUNC) { int l = bm0 + 128; kEnd = (l < segK) ? l : segK; }
    const int cps   = kEnd >> 5;          // 32-elem chunks per segment
    const int total = 3 * cps;

    float acc[4][4][4] = {};

    auto load_chunk = [&](int c, int buf) {
        int seg = c / cps, ck = c - seg * cps;
        const __nv_bfloat16* Aseg = (seg == 1) ? A1 : A0;
        const __nv_bfloat16* Bseg = (seg == 2) ? B1 : B0;
        const __nv_bfloat16* gA = Aseg + (size_t)bm0 * ldA + (ck << 5);
        const __nv_bfloat16* gB = Bseg + (size_t)bn0 * ldB + (ck << 5);
        const uint32_t bA = s2u(&smA[buf][0]);
        const uint32_t bB = s2u(&smB[buf][0]);
        #pragma unroll
        for (int t = 0; t < 2; ++t) {
            int f = tid + t * 256;            // 0..511
            int row = f >> 2, cch = f & 3;
            int sw = cch ^ ((row >> 1) & 3);
            CPA16(bA + row * 64 + sw * 16, (const char*)(gA + (size_t)row * ldA) + cch * 16);
            CPA16(bB + row * 64 + sw * 16, (const char*)(gB + (size_t)row * ldB) + cch * 16);
        }
        asm volatile("cp.async.commit_group;" ::: "memory");
    };

    load_chunk(0, 0);

    for (int c = 0; c < total; ++c) {
        if (c + 1 < total) {
            load_chunk(c + 1, (c + 1) & 1);
            asm volatile("cp.async.wait_group 1;" ::: "memory");
        } else {
            asm volatile("cp.async.wait_group 0;" ::: "memory");
        }
        __syncthreads();

        const int buf = c & 1;
        const uint32_t bA = s2u(&smA[buf][0]);
        const uint32_t bB = s2u(&smB[buf][0]);

        #pragma unroll
        for (int ks = 0; ks < 2; ++ks) {
            uint32_t a[4][4];
            #pragma unroll
            for (int mf = 0; mf < 4; ++mf) {
                int blk = lane >> 3, wi = lane & 7;
                int row = warp_m + mf * 16 + (blk & 1) * 8 + wi;
                int cch = ks * 2 + (blk >> 1);
                LDSM_X4(a[mf], bA + row * 64 + (cch ^ ((row >> 1) & 3)) * 16);
            }
            uint32_t b[4][2];
            #pragma unroll
            for (int nf = 0; nf < 4; ++nf) {
                int blk = (lane >> 3) & 1, wi = lane & 7;
                int row = warp_n + nf * 8 + wi;
                int cch = ks * 2 + blk;
                LDSM_X2(b[nf], bB + row * 64 + (cch ^ ((row >> 1) & 3)) * 16);
            }
            #pragma unroll
            for (int mf = 0; mf < 4; ++mf)
                #pragma unroll
                for (int nf = 0; nf < 4; ++nf)
                    MMA16816(acc[mf][nf], a[mf], b[nf]);
        }
        __syncthreads();
    }

    // ---- epilogue: c-frag mapping: c0,c1 -> (row = lane/4, col = (lane%4)*2),
    //                c2,c3 -> row+8 ----
    const int rq = lane >> 2, cq = (lane & 3) * 2;
    #pragma unroll
    for (int mf = 0; mf < 4; ++mf) {
        #pragma unroll
        for (int nf = 0; nf < 4; ++nf) {
            int m0 = bm0 + warp_m + mf * 16 + rq;
            int n0 = bn0 + warp_n + nf * 8 + cq;
            if (EPI == 0) {
                float* base = Cf + z * sC;
                *(float2*)(base + (size_t)m0 * ldC + n0) =
                    make_float2(acc[mf][nf][0], acc[mf][nf][1]);
                *(float2*)(base + (size_t)(m0 + 8) * ldC + n0) =
                    make_float2(acc[mf][nf][2], acc[mf][nf][3]);
            } else {
                #pragma unroll
                for (int h = 0; h < 2; ++h) {
                    float v0 = acc[mf][nf][2 * h + 0];
                    float v1 = acc[mf][nf][2 * h + 1];
                    __nv_bfloat16 h0 = __float2bfloat16(v0);
                    __nv_bfloat16 h1 = __float2bfloat16(v1);
                    __nv_bfloat162 HH, LL;
                    HH.x = h0; HH.y = h1;
                    LL.x = __float2bfloat16(v0 - __bfloat162float(h0));
                    LL.y = __float2bfloat16(v1 - __bfloat162float(h1));
                    size_t off = (size_t)(m0 + 8 * h) * ldC + n0;
                    *(__nv_bfloat162*)(Ch + off) = HH;
                    *(__nv_bfloat162*)(Cl + off) = LL;
                }
            }
        }
    }
}

// ---------------------------------------------------------------------------
// fp32 -> bf16 (hi, lo) split, elementwise
// ---------------------------------------------------------------------------
__global__ void __launch_bounds__(256) split_kernel(
    const float* __restrict__ x, __nv_bfloat16* __restrict__ h,
    __nv_bfloat16* __restrict__ l, int n)
{
    int i = (blockIdx.x * 256 + threadIdx.x) * 8;
    if (i >= n) return;
    float4 a = *(const float4*)(x + i);
    float4 b = *(const float4*)(x + i + 4);
    float v[8] = {a.x, a.y, a.z, a.w, b.x, b.y, b.z, b.w};
    union { __nv_bfloat16 bb[8]; uint4 u; } H, L;
    #pragma unroll
    for (int j = 0; j < 8; ++j) {
        __nv_bfloat16 hh = __float2bfloat16(v[j]);
        H.bb[j] = hh;
        L.bb[j] = __float2bfloat16(v[j] - __bfloat162float(hh));
    }
    *(uint4*)(h + i) = H.u;
    *(uint4*)(l + i) = L.u;
}

// W [DM x 512] fp32 -> Wt hi/lo [512 x DM] bf16 (transposed, K-major)
__global__ void __launch_bounds__(256) splitw_kernel(
    const float* __restrict__ W, __nv_bfloat16* __restrict__ h,
    __nv_bfloat16* __restrict__ l)
{
    int o = blockIdx.x * 256 + threadIdx.x;   // o = n*DM + k, n<512
    int n = o >> 10, k = o & 1023;
    float v = W[(size_t)k * 512 + n];
    __nv_bfloat16 hh = __float2bfloat16(v);
    h[o] = hh;
    l[o] = __float2bfloat16(v - __bfloat162float(hh));
}

// ---------------------------------------------------------------------------
// fused mask + softmax reading fp32 scores, writing bf16 hi/lo probabilities
// one CTA (256 thr) per row; thread t owns cols [8t, 8t+8)
// ---------------------------------------------------------------------------
__global__ void __launch_bounds__(256) softmax_split(
    const float* __restrict__ S, __nv_bfloat16* __restrict__ Ph,
    __nv_bfloat16* __restrict__ Pl,
    const int* __restrict__ qpad, const int* __restrict__ kpad, float scale)
{
    const int r = blockIdx.x;
    const int b = r >> 11, i = r & (SS - 1);
    const float* row = S + (size_t)r * SS;
    const int* kp = kpad + b * SS;
    const bool qp = (qpad[r] != 0);
    const int tid = threadIdx.x, j0 = tid * 8;
    const int lane = tid & 31, warp = tid >> 5;

    float4 a = ((const float4*)(row + j0))[0];
    float4 c = ((const float4*)(row + j0))[1];
    int4 ka = ((const int4*)(kp + j0))[0];
    int4 kb = ((const int4*)(kp + j0))[1];
    float x[8] = {a.x, a.y, a.z, a.w, c.x, c.y, c.z, c.w};
    int km[8] = {ka.x, ka.y, ka.z, ka.w, kb.x, kb.y, kb.z, kb.w};

    float m = -INFINITY;
    #pragma unroll
    for (int u = 0; u < 8; ++u) {
        bool valid = (!qp) && (j0 + u <= i) && (km[u] == 0);
        x[u] = valid ? x[u] * scale : -INFINITY;
        m = fmaxf(m, x[u]);
    }

    __shared__ float redm[8], reds[8];
    #pragma unroll
    for (int o = 16; o; o >>= 1) m = fmaxf(m, __shfl_xor_sync(0xffffffffu, m, o));
    if (lane == 0) redm[warp] = m;
    __syncthreads();
    float bm = -INFINITY;
    #pragma unroll
    for (int w = 0; w < 8; ++w) bm = fmaxf(bm, redm[w]);

    uint4* oh = (uint4*)(Ph + (size_t)r * SS + j0);
    uint4* ol = (uint4*)(Pl + (size_t)r * SS + j0);

    if (bm == -INFINITY) {     // fully masked row -> zeros
        uint4 zz = make_uint4(0, 0, 0, 0);
        *oh = zz; *ol = zz;
        return;
    }

    float e[8];
    float s = 0.0f;
    #pragma unroll
    for (int u = 0; u < 8; ++u) {
        e[u] = (x[u] == -INFINITY) ? 0.0f : __expf(x[u] - bm);
        s += e[u];
    }
    #pragma unroll
    for (int o = 16; o; o >>= 1) s += __shfl_xor_sync(0xffffffffu, s, o);
    if (lane == 0) reds[warp] = s;
    __syncthreads();
    float bs = 0.0f;
    #pragma unroll
    for (int w = 0; w < 8; ++w) bs += reds[w];

    const float rinv = 1.0f / bs;
    union { __nv_bfloat16 bb[8]; uint4 u; } H, L;
    #pragma unroll
    for (int u = 0; u < 8; ++u) {
        float p = e[u] * rinv;
        __nv_bfloat16 hh = __float2bfloat16(p);
        H.bb[u] = hh;
        L.bb[u] = __float2bfloat16(p - __bfloat162float(hh));
    }
    *oh = H.u;
    *ol = L.u;
}

// ---------------------------------------------------------------------------
extern "C" void kernel_launch(void* const* d_in, const int* in_sizes, int n_in,
                              void* d_out, int out_size)
{
    const float* sq   = (const float*)d_in[0];
    const float* skv  = (const float*)d_in[1];
    const int*   qpad = (const int*)d_in[2];
    const int*   kpad = (const int*)d_in[3];
    const float* Wq   = (const float*)d_in[4];
    const float* Wk   = (const float*)d_in[5];
    const float* Wv   = (const float*)d_in[6];
    float* out = (float*)d_out;

    float *Sb;
    __nv_bfloat16 *sqh, *sql, *kvh, *kvl, *wqh, *wql, *wkh, *wkl, *wvh, *wvl;
    __nv_bfloat16 *qh, *ql, *kh, *kl, *vth, *vtl, *pH, *pL;
    cudaGetSymbolAddress((void**)&Sb,  g_S);
    cudaGetSymbolAddress((void**)&sqh, g_sqh); cudaGetSymbolAddress((void**)&sql, g_sql);
    cudaGetSymbolAddress((void**)&kvh, g_kvh); cudaGetSymbolAddress((void**)&kvl, g_kvl);
    cudaGetSymbolAddress((void**)&wqh, g_wqh); cudaGetSymbolAddress((void**)&wql, g_wql);
    cudaGetSymbolAddress((void**)&wkh, g_wkh); cudaGetSymbolAddress((void**)&wkl, g_wkl);
    cudaGetSymbolAddress((void**)&wvh, g_wvh); cudaGetSymbolAddress((void**)&wvl, g_wvl);
    cudaGetSymbolAddress((void**)&qh,  g_qh);  cudaGetSymbolAddress((void**)&ql,  g_ql);
    cudaGetSymbolAddress((void**)&kh,  g_kh);  cudaGetSymbolAddress((void**)&kl,  g_kl);
    cudaGetSymbolAddress((void**)&vth, g_vth); cudaGetSymbolAddress((void**)&vtl, g_vtl);
    cudaGetSymbolAddress((void**)&pH,  g_ph);  cudaGetSymbolAddress((void**)&pL,  g_pl);

    // 1) split sources to bf16 hi/lo
    const int nsrc = MTOK * DM;                    // 16.7M
    split_kernel<<<nsrc / 2048, 256>>>(sq,  sqh, sql, nsrc);
    split_kernel<<<nsrc / 2048, 256>>>(skv, kvh, kvl, nsrc);
    // 2) split + transpose weights
    splitw_kernel<<<(DK * DM) / 256, 256>>>(Wq, wqh, wql);
    splitw_kernel<<<(DK * DM) / 256, 256>>>(Wk, wkh, wkl);
    splitw_kernel<<<(DV * DM) / 256, 256>>>(Wv, wvh, wvl);

    // 3) Q = sq*Wq  [16384 x 512], split-epilogue
    mma_gemm<false, false, 1><<<dim3(DK / 128, MTOK / 128, 1), 256>>>(
        sqh, sql, wqh, wql, nullptr, qh, ql, DM, DM, DM, DK, 0, 0, 0);
    // 4) K = skv*Wk
    mma_gemm<false, false, 1><<<dim3(DK / 128, MTOK / 128, 1), 256>>>(
        kvh, kvl, wkh, wkl, nullptr, kh, kl, DM, DM, DM, DK, 0, 0, 0);
    // 5) Vt = Wv^T * skv^T  [512 x 16384], split-epilogue (produced transposed)
    mma_gemm<false, false, 1><<<dim3(MTOK / 128, DV / 128, 1), 256>>>(
        wvh, wvl, kvh, kvl, nullptr, vth, vtl, DM, DM, DM, MTOK, 0, 0, 0);

    // 6) scores S_b = Q_b * K_b^T (causal tile-skip), fp32 epilogue
    mma_gemm<true, false, 0><<<dim3(SS / 128, SS / 128, BB), 256>>>(
        qh, ql, kh, kl, Sb, nullptr, nullptr, DK, DK, DK, SS,
        (long long)SS * DK, (long long)SS * DK, (long long)SS * SS);

    // 7) mask + softmax -> P hi/lo bf16
    const float scale = 0.04419417382415922f;   // 1/sqrt(512)
    softmax_split<<<MTOK, 256>>>(Sb, pH, pL, qpad, kpad, scale);

    // 8) O_b = P_b * V_b  (K truncated at causal diagonal), fp32 epilogue -> out
    mma_gemm<false, true, 0><<<dim3(DV / 128, SS / 128, BB), 256>>>(
        pH, pL, vth, vtl, out, nullptr, nullptr, SS, SS, MTOK, DV,
        (long long)SS * SS, (long long)SS, (long long)SS * DV);
}

// round 5
// speedup vs baseline: 2.7618x; 1.1014x over previous
#include <cuda_runtime.h>
#include <cuda_bf16.h>
#include <stdint.h>
#include <math.h>

#define BB 8
#define SS 2048
#define DM 1024
#define DK 512
#define DV 512
#define MTOK (BB*SS)   // 16384

// ---------------- scratch (static device allocations) ----------------
__device__ __align__(256) float         g_S  [(size_t)BB*SS*SS];      // 134 MB scores
__device__ __align__(256) __nv_bfloat16 g_sqh[(size_t)MTOK*DM];
__device__ __align__(256) __nv_bfloat16 g_sql[(size_t)MTOK*DM];
__device__ __align__(256) __nv_bfloat16 g_kvh[(size_t)MTOK*DM];
__device__ __align__(256) __nv_bfloat16 g_kvl[(size_t)MTOK*DM];
__device__ __align__(256) __nv_bfloat16 g_wqh[(size_t)DK*DM];
__device__ __align__(256) __nv_bfloat16 g_wql[(size_t)DK*DM];
__device__ __align__(256) __nv_bfloat16 g_wkh[(size_t)DK*DM];
__device__ __align__(256) __nv_bfloat16 g_wkl[(size_t)DK*DM];
__device__ __align__(256) __nv_bfloat16 g_wvh[(size_t)DV*DM];
__device__ __align__(256) __nv_bfloat16 g_wvl[(size_t)DV*DM];
__device__ __align__(256) __nv_bfloat16 g_qh [(size_t)MTOK*DK];
__device__ __align__(256) __nv_bfloat16 g_ql [(size_t)MTOK*DK];
__device__ __align__(256) __nv_bfloat16 g_kh [(size_t)MTOK*DK];
__device__ __align__(256) __nv_bfloat16 g_kl [(size_t)MTOK*DK];
__device__ __align__(256) __nv_bfloat16 g_vth[(size_t)DV*MTOK];      // V^T: [512 x 16384]
__device__ __align__(256) __nv_bfloat16 g_vtl[(size_t)DV*MTOK];
__device__ __align__(256) __nv_bfloat16 g_ph [(size_t)MTOK*SS];      // P hi
__device__ __align__(256) __nv_bfloat16 g_pl [(size_t)MTOK*SS];      // P lo

// ---------------- portable PTX helpers (sm_80+ only) ----------
__device__ __forceinline__ uint32_t s2u(const void* p) {
    return (uint32_t)__cvta_generic_to_shared(p);
}

#define CPA16(dst, src) \
    asm volatile("cp.async.cg.shared.global [%0], [%1], 16;" :: "r"(dst), "l"(src))

#define LDSM_X4(r, addr) \
    asm volatile("ldmatrix.sync.aligned.m8n8.x4.shared.b16 {%0,%1,%2,%3}, [%4];" \
        : "=r"((r)[0]), "=r"((r)[1]), "=r"((r)[2]), "=r"((r)[3]) : "r"(addr))

#define MMA16816(d, a, b) \
    asm volatile("mma.sync.aligned.m16n8k16.row.col.f32.bf16.bf16.f32 " \
        "{%0,%1,%2,%3}, {%4,%5,%6,%7}, {%8,%9}, {%0,%1,%2,%3};" \
        : "+f"((d)[0]), "+f"((d)[1]), "+f"((d)[2]), "+f"((d)[3]) \
        : "r"((a)[0]), "r"((a)[1]), "r"((a)[2]), "r"((a)[3]), \
          "r"((b)[0]), "r"((b)[1]))

// ---------------------------------------------------------------------------
// bf16 MMA GEMM:  C[M x N] = sum over 3 segments of Aseg[M x segK] * Bseg[N x segK]^T
//   seg 0: (A0,B0)  seg 1: (A1,B0)  seg 2: (A0,B1)     (3-term bf16 split)
//   Operands K-major row-major bf16. 128x128 CTA tile, BK=64, double-buffered.
//   Smem: row = 64 bf16 = 128 B = 8 x 16B chunks; chunk c stored at c^(row&7).
//   CSKIP: skip tiles strictly above causal diagonal
//   KTRUNC: per-segment K truncated at bm0+128 (attn*V causal)
//   EPI: 0 -> fp32 to Cf ; 1 -> bf16 hi/lo split to Ch/Cl
// ---------------------------------------------------------------------------
template <bool CSKIP, bool KTRUNC, int EPI>
__global__ void __launch_bounds__(256, 2) mma_gemm(
    const __nv_bfloat16* __restrict__ A0, const __nv_bfloat16* __restrict__ A1,
    const __nv_bfloat16* __restrict__ B0, const __nv_bfloat16* __restrict__ B1,
    float* __restrict__ Cf, __nv_bfloat16* __restrict__ Ch, __nv_bfloat16* __restrict__ Cl,
    int segK, int ldA, int ldB, int ldC,
    long long sA, long long sB, long long sC)
{
    extern __shared__ char sm[];
    // per buffer: A 128x64 bf16 = 16 KB, B 16 KB
    const uint32_t smb = s2u(sm);
    const uint32_t aBuf[2] = { smb,          smb + 16384 };
    const uint32_t bBuf[2] = { smb + 32768,  smb + 49152 };

    const int bn0 = blockIdx.x * 128;
    const int bm0 = blockIdx.y * 128;
    if (CSKIP && bn0 >= bm0 + 128) return;

    const long long z = blockIdx.z;
    A0 += z * sA; A1 += z * sA; B0 += z * sB; B1 += z * sB;

    const int tid = threadIdx.x, wid = tid >> 5, lane = tid & 31;
    const int warp_m = (wid >> 2) * 64;   // 0 or 64
    const int warp_n = (wid & 3) * 32;    // 0,32,64,96

    int kEnd = segK;
    if (KTRUNC) { int l = bm0 + 128; kEnd = (l < segK) ? l : segK; }
    const int cps   = kEnd >> 6;          // 64-elem chunks per segment
    const int total = 3 * cps;

    float acc[4][4][4] = {};

    auto load_chunk = [&](int c, int buf) {
        int seg = c / cps, ck = c - seg * cps;
        const __nv_bfloat16* Aseg = (seg == 1) ? A1 : A0;
        const __nv_bfloat16* Bseg = (seg == 2) ? B1 : B0;
        const __nv_bfloat16* gA = Aseg + (size_t)bm0 * ldA + (ck << 6);
        const __nv_bfloat16* gB = Bseg + (size_t)bn0 * ldB + (ck << 6);
        const uint32_t bA = aBuf[buf], bB = bBuf[buf];
        #pragma unroll
        for (int t = 0; t < 4; ++t) {
            int f = tid + t * 256;            // 0..1023
            int row = f >> 3, cch = f & 7;
            int sw = cch ^ (row & 7);
            CPA16(bA + row * 128 + sw * 16, (const char*)(gA + (size_t)row * ldA) + cch * 16);
            CPA16(bB + row * 128 + sw * 16, (const char*)(gB + (size_t)row * ldB) + cch * 16);
        }
        asm volatile("cp.async.commit_group;" ::: "memory");
    };

    load_chunk(0, 0);

    const int wi = lane & 7, g = lane >> 3;   // ldmatrix lane-group decomposition

    for (int c = 0; c < total; ++c) {
        if (c + 1 < total) {
            load_chunk(c + 1, (c + 1) & 1);
            asm volatile("cp.async.wait_group 1;" ::: "memory");
        } else {
            asm volatile("cp.async.wait_group 0;" ::: "memory");
        }
        __syncthreads();

        const int buf = c & 1;
        const uint32_t bA = aBuf[buf], bB = bBuf[buf];

        #pragma unroll
        for (int ks = 0; ks < 4; ++ks) {
            // A frags: x4 -> mats (m+wi,k0), (m+8+wi,k0), (m+wi,k1), (m+8+wi,k1)
            uint32_t a[4][4];
            #pragma unroll
            for (int mf = 0; mf < 4; ++mf) {
                int row = warp_m + mf * 16 + (g & 1) * 8 + wi;
                int cch = 2 * ks + (g >> 1);
                LDSM_X4(a[mf], bA + row * 128 + (cch ^ (row & 7)) * 16);
            }
            // B frags: x4 packs 2 n-frags -> mats (n+wi,k0),(n+wi,k1),(n+8+wi,k0),(n+8+wi,k1)
            uint32_t b[4][2];
            #pragma unroll
            for (int p = 0; p < 2; ++p) {
                uint32_t r[4];
                int row = warp_n + p * 16 + (g >> 1) * 8 + wi;
                int cch = 2 * ks + (g & 1);
                LDSM_X4(r, bB + row * 128 + (cch ^ (row & 7)) * 16);
                b[2 * p + 0][0] = r[0]; b[2 * p + 0][1] = r[1];
                b[2 * p + 1][0] = r[2]; b[2 * p + 1][1] = r[3];
            }
            #pragma unroll
            for (int mf = 0; mf < 4; ++mf)
                #pragma unroll
                for (int nf = 0; nf < 4; ++nf)
                    MMA16816(acc[mf][nf], a[mf], b[nf]);
        }
        __syncthreads();
    }

    // ---- epilogue: c0,c1 -> (row = lane/4, col = (lane%4)*2), c2,c3 -> row+8 ----
    const int rq = lane >> 2, cq = (lane & 3) * 2;
    #pragma unroll
    for (int mf = 0; mf < 4; ++mf) {
        #pragma unroll
        for (int nf = 0; nf < 4; ++nf) {
            int m0 = bm0 + warp_m + mf * 16 + rq;
            int n0 = bn0 + warp_n + nf * 8 + cq;
            if (EPI == 0) {
                float* base = Cf + z * sC;
                *(float2*)(base + (size_t)m0 * ldC + n0) =
                    make_float2(acc[mf][nf][0], acc[mf][nf][1]);
                *(float2*)(base + (size_t)(m0 + 8) * ldC + n0) =
                    make_float2(acc[mf][nf][2], acc[mf][nf][3]);
            } else {
                #pragma unroll
                for (int h = 0; h < 2; ++h) {
                    float v0 = acc[mf][nf][2 * h + 0];
                    float v1 = acc[mf][nf][2 * h + 1];
                    __nv_bfloat16 h0 = __float2bfloat16(v0);
                    __nv_bfloat16 h1 = __float2bfloat16(v1);
                    __nv_bfloat162 HH, LL;
                    HH.x = h0; HH.y = h1;
                    LL.x = __float2bfloat16(v0 - __bfloat162float(h0));
                    LL.y = __float2bfloat16(v1 - __bfloat162float(h1));
                    size_t off = (size_t)(m0 + 8 * h) * ldC + n0;
                    *(__nv_bfloat162*)(Ch + off) = HH;
                    *(__nv_bfloat162*)(Cl + off) = LL;
                }
            }
        }
    }
}

// ---------------------------------------------------------------------------
// fp32 -> bf16 (hi, lo) split for both sources in one launch (grid.y selects)
// ---------------------------------------------------------------------------
__global__ void __launch_bounds__(256) split2_kernel(
    const float* __restrict__ x0, __nv_bfloat16* __restrict__ h0, __nv_bfloat16* __restrict__ l0,
    const float* __restrict__ x1, __nv_bfloat16* __restrict__ h1, __nv_bfloat16* __restrict__ l1)
{
    const float* x = blockIdx.y ? x1 : x0;
    __nv_bfloat16* h = blockIdx.y ? h1 : h0;
    __nv_bfloat16* l = blockIdx.y ? l1 : l0;
    int i = (blockIdx.x * 256 + threadIdx.x) * 8;
    float4 a = *(const float4*)(x + i);
    float4 b = *(const float4*)(x + i + 4);
    float v[8] = {a.x, a.y, a.z, a.w, b.x, b.y, b.z, b.w};
    union { __nv_bfloat16 bb[8]; uint4 u; } H, L;
    #pragma unroll
    for (int j = 0; j < 8; ++j) {
        __nv_bfloat16 hh = __float2bfloat16(v[j]);
        H.bb[j] = hh;
        L.bb[j] = __float2bfloat16(v[j] - __bfloat162float(hh));
    }
    *(uint4*)(h + i) = H.u;
    *(uint4*)(l + i) = L.u;
}

// W [DM x 512] fp32 -> Wt hi/lo [512 x DM] bf16 (transposed, K-major)
__global__ void __launch_bounds__(256) splitw_kernel(
    const float* __restrict__ W, __nv_bfloat16* __restrict__ h,
    __nv_bfloat16* __restrict__ l)
{
    int o = blockIdx.x * 256 + threadIdx.x;   // o = n*DM + k, n<512
    int n = o >> 10, k = o & 1023;
    float v = W[(size_t)k * 512 + n];
    __nv_bfloat16 hh = __float2bfloat16(v);
    h[o] = hh;
    l[o] = __float2bfloat16(v - __bfloat162float(hh));
}

// ---------------------------------------------------------------------------
// fused mask + softmax reading fp32 scores, writing bf16 hi/lo probabilities
// ---------------------------------------------------------------------------
__global__ void __launch_bounds__(256) softmax_split(
    const float* __restrict__ S, __nv_bfloat16* __restrict__ Ph,
    __nv_bfloat16* __restrict__ Pl,
    const int* __restrict__ qpad, const int* __restrict__ kpad, float scale)
{
    const int r = blockIdx.x;
    const int b = r >> 11, i = r & (SS - 1);
    const float* row = S + (size_t)r * SS;
    const int* kp = kpad + b * SS;
    const bool qp = (qpad[r] != 0);
    const int tid = threadIdx.x, j0 = tid * 8;
    const int lane = tid & 31, warp = tid >> 5;

    float4 a = ((const float4*)(row + j0))[0];
    float4 c = ((const float4*)(row + j0))[1];
    int4 ka = ((const int4*)(kp + j0))[0];
    int4 kb = ((const int4*)(kp + j0))[1];
    float x[8] = {a.x, a.y, a.z, a.w, c.x, c.y, c.z, c.w};
    int km[8] = {ka.x, ka.y, ka.z, ka.w, kb.x, kb.y, kb.z, kb.w};

    float m = -INFINITY;
    #pragma unroll
    for (int u = 0; u < 8; ++u) {
        bool valid = (!qp) && (j0 + u <= i) && (km[u] == 0);
        x[u] = valid ? x[u] * scale : -INFINITY;
        m = fmaxf(m, x[u]);
    }

    __shared__ float redm[8], reds[8];
    #pragma unroll
    for (int o = 16; o; o >>= 1) m = fmaxf(m, __shfl_xor_sync(0xffffffffu, m, o));
    if (lane == 0) redm[warp] = m;
    __syncthreads();
    float bm = -INFINITY;
    #pragma unroll
    for (int w = 0; w < 8; ++w) bm = fmaxf(bm, redm[w]);

    uint4* oh = (uint4*)(Ph + (size_t)r * SS + j0);
    uint4* ol = (uint4*)(Pl + (size_t)r * SS + j0);

    if (bm == -INFINITY) {     // fully masked row -> zeros
        uint4 zz = make_uint4(0, 0, 0, 0);
        *oh = zz; *ol = zz;
        return;
    }

    float e[8];
    float s = 0.0f;
    #pragma unroll
    for (int u = 0; u < 8; ++u) {
        e[u] = (x[u] == -INFINITY) ? 0.0f : __expf(x[u] - bm);
        s += e[u];
    }
    #pragma unroll
    for (int o = 16; o; o >>= 1) s += __shfl_xor_sync(0xffffffffu, s, o);
    if (lane == 0) reds[warp] = s;
    __syncthreads();
    float bs = 0.0f;
    #pragma unroll
    for (int w = 0; w < 8; ++w) bs += reds[w];

    const float rinv = 1.0f / bs;
    union { __nv_bfloat16 bb[8]; uint4 u; } H, L;
    #pragma unroll
    for (int u = 0; u < 8; ++u) {
        float p = e[u] * rinv;
        __nv_bfloat16 hh = __float2bfloat16(p);
        H.bb[u] = hh;
        L.bb[u] = __float2bfloat16(p - __bfloat162float(hh));
    }
    *oh = H.u;
    *ol = L.u;
}

// ---------------------------------------------------------------------------
extern "C" void kernel_launch(void* const* d_in, const int* in_sizes, int n_in,
                              void* d_out, int out_size)
{
    const float* sq   = (const float*)d_in[0];
    const float* skv  = (const float*)d_in[1];
    const int*   qpad = (const int*)d_in[2];
    const int*   kpad = (const int*)d_in[3];
    const float* Wq   = (const float*)d_in[4];
    const float* Wk   = (const float*)d_in[5];
    const float* Wv   = (const float*)d_in[6];
    float* out = (float*)d_out;

    float *Sb;
    __nv_bfloat16 *sqh, *sql, *kvh, *kvl, *wqh, *wql, *wkh, *wkl, *wvh, *wvl;
    __nv_bfloat16 *qh, *ql, *kh, *kl, *vth, *vtl, *pH, *pL;
    cudaGetSymbolAddress((void**)&Sb,  g_S);
    cudaGetSymbolAddress((void**)&sqh, g_sqh); cudaGetSymbolAddress((void**)&sql, g_sql);
    cudaGetSymbolAddress((void**)&kvh, g_kvh); cudaGetSymbolAddress((void**)&kvl, g_kvl);
    cudaGetSymbolAddress((void**)&wqh, g_wqh); cudaGetSymbolAddress((void**)&wql, g_wql);
    cudaGetSymbolAddress((void**)&wkh, g_wkh); cudaGetSymbolAddress((void**)&wkl, g_wkl);
    cudaGetSymbolAddress((void**)&wvh, g_wvh); cudaGetSymbolAddress((void**)&wvl, g_wvl);
    cudaGetSymbolAddress((void**)&qh,  g_qh);  cudaGetSymbolAddress((void**)&ql,  g_ql);
    cudaGetSymbolAddress((void**)&kh,  g_kh);  cudaGetSymbolAddress((void**)&kl,  g_kl);
    cudaGetSymbolAddress((void**)&vth, g_vth); cudaGetSymbolAddress((void**)&vtl, g_vtl);
    cudaGetSymbolAddress((void**)&pH,  g_ph);  cudaGetSymbolAddress((void**)&pL,  g_pl);

    const int SMEMSZ = 65536;   // 2 x (16 KB A + 16 KB B)
    cudaFuncSetAttribute(mma_gemm<false, false, 1>,
                         cudaFuncAttributeMaxDynamicSharedMemorySize, SMEMSZ);
    cudaFuncSetAttribute(mma_gemm<true, false, 0>,
                         cudaFuncAttributeMaxDynamicSharedMemorySize, SMEMSZ);
    cudaFuncSetAttribute(mma_gemm<false, true, 0>,
                         cudaFuncAttributeMaxDynamicSharedMemorySize, SMEMSZ);

    // 1) split both sources to bf16 hi/lo (one launch)
    const int nsrc = MTOK * DM;                    // 16.7M
    split2_kernel<<<dim3(nsrc / 2048, 2), 256>>>(sq, sqh, sql, skv, kvh, kvl);
    // 2) split + transpose weights
    splitw_kernel<<<(DK * DM) / 256, 256>>>(Wq, wqh, wql);
    splitw_kernel<<<(DK * DM) / 256, 256>>>(Wk, wkh, wkl);
    splitw_kernel<<<(DV * DM) / 256, 256>>>(Wv, wvh, wvl);

    // 3) Q = sq*Wq  [16384 x 512], split-epilogue
    mma_gemm<false, false, 1><<<dim3(DK / 128, MTOK / 128, 1), 256, SMEMSZ>>>(
        sqh, sql, wqh, wql, nullptr, qh, ql, DM, DM, DM, DK, 0, 0, 0);
    // 4) K = skv*Wk
    mma_gemm<false, false, 1><<<dim3(DK / 128, MTOK / 128, 1), 256, SMEMSZ>>>(
        kvh, kvl, wkh, wkl, nullptr, kh, kl, DM, DM, DM, DK, 0, 0, 0);
    // 5) Vt = Wv^T * skv^T  [512 x 16384], split-epilogue (produced transposed)
    mma_gemm<false, false, 1><<<dim3(MTOK / 128, DV / 128, 1), 256, SMEMSZ>>>(
        wvh, wvl, kvh, kvl, nullptr, vth, vtl, DM, DM, DM, MTOK, 0, 0, 0);

    // 6) scores S_b = Q_b * K_b^T (causal tile-skip), fp32 epilogue
    mma_gemm<true, false, 0><<<dim3(SS / 128, SS / 128, BB), 256, SMEMSZ>>>(
        qh, ql, kh, kl, Sb, nullptr, nullptr, DK, DK, DK, SS,
        (long long)SS * DK, (long long)SS * DK, (long long)SS * SS);

    // 7) mask + softmax -> P hi/lo bf16
    const float scale = 0.04419417382415922f;   // 1/sqrt(512)
    softmax_split<<<MTOK, 256>>>(Sb, pH, pL, qpad, kpad, scale);

    // 8) O_b = P_b * V_b  (K truncated at causal diagonal), fp32 epilogue -> out
    mma_gemm<false, true, 0><<<dim3(DV / 128, SS / 128, BB), 256, SMEMSZ>>>(
        pH, pL, vth, vtl, out, nullptr, nullptr, SS, SS, MTOK, DV,
        (long long)SS * SS, (long long)SS, (long long)SS * DV);
}